// round 15
// baseline (speedup 1.0000x reference)
#include <cuda_runtime.h>
#include <math.h>

// ---------------------------------------------------------------------------
// ProteinEmbeddingPooling — R14 structure (76.3us best), single change:
// combine folded into attn's tail (last-CTA-per-batch pattern) — removes one
// kernel + launch gap; combine work hides under other batches' attn CTAs.
// ---------------------------------------------------------------------------

#define BB 32
#define SS 1024
#define DD 1280
#define CTAS_PER_B 16
#define WPB 4
#define NCP CTAS_PER_B                   // attn partials per batch
#define RPW (SS / (CTAS_PER_B * WPB))    // 16 rows per warp

// ---- scratch (device globals; no allocation allowed) ----
__device__ float g_q0[BB * DD];
__device__ float g_kq[BB * DD];
__device__ float g_ctx[BB * DD];
__device__ float g_h[BB * DD];
__device__ float g_pm[BB * NCP];
__device__ float g_pl[BB * NCP];
__device__ float g_pacc[(size_t)BB * NCP * DD];      // 2.6 MB
__device__ float g_pooled[BB * DD];
__device__ unsigned g_cnt[BB];                       // attn arrival tickets

__device__ __forceinline__ void red_add_v4(float* p, float a, float b,
                                           float c, float d)
{
    asm volatile("red.global.add.v4.f32 [%0], {%1, %2, %3, %4};"
                 :: "l"(p), "f"(a), "f"(b), "f"(c), "f"(d) : "memory");
}

// ---------------------------------------------------------------------------
// init: bias-seed C matrices + reset per-batch tickets (runs first each replay)
// ---------------------------------------------------------------------------
__global__ void init_kernel(const float* __restrict__ bq,
                            const float* __restrict__ bv,
                            const float* __restrict__ bo)
{
    int i = blockIdx.x * blockDim.x + threadIdx.x;
    if (i < BB * DD) {
        int n = i % DD;
        g_q0[i]  = bq[n];
        g_kq[i]  = 0.0f;
        g_ctx[i] = bv[n];
        g_h[i]   = bo[n];
    }
    if (i < BB) g_cnt[i] = 0u;
}

// ---------------------------------------------------------------------------
// small GEMM: C[32,1280] += A[32,1280] * op(W)   (R14-exact: 4m x 4n tile)
//   MODE 0: W [N,K] row-major (C = A.W^T) ; MODE 1: W [K,N] row-major (C = A.W)
//   SRC: 0 = Aext(lda), 1 = g_q0, 2 = g_pooled, 3 = g_ctx (device-resolved)
//   DST: 0 = g_q0, 1 = g_kq, 2 = g_ctx, 3 = g_h
// grid (20, 32), block 128. Epilogue: red.global.add.v4.f32 x4 per thread.
// ---------------------------------------------------------------------------
template<int MODE, int SRC, int DST>
__global__ void __launch_bounds__(128) gemm32(const float* __restrict__ Aext,
                                              size_t lda,
                                              const float* __restrict__ W)
{
    constexpr int NT = 64;
    constexpr int KC = 40;

    const float* A = (SRC == 0) ? Aext
                   : (SRC == 1) ? g_q0
                   : (SRC == 2) ? g_pooled
                   :              g_ctx;
    if (SRC != 0) lda = DD;
    float* C = (DST == 0) ? g_q0
             : (DST == 1) ? g_kq
             : (DST == 2) ? g_ctx
             :              g_h;

    __shared__ float As[KC][33];     // [k][m]
    __shared__ float Ws[KC][68];     // [k][n]

    const int tid = threadIdx.x;     // 0..127
    const int n0 = blockIdx.x * NT;
    const int k0 = blockIdx.y * KC;
    const int k04 = k0 >> 2;

    const float4* A4 = reinterpret_cast<const float4*>(A);
    const size_t lda4 = lda >> 2;
#pragma unroll
    for (int i = 0; i < 3; i++) {
        int f = tid + i * 128;
        if (f < 320) {
            int m = f / 10, kc4 = f % 10;
            float4 v = A4[(size_t)m * lda4 + k04 + kc4];
            As[kc4 * 4 + 0][m] = v.x;
            As[kc4 * 4 + 1][m] = v.y;
            As[kc4 * 4 + 2][m] = v.z;
            As[kc4 * 4 + 3][m] = v.w;
        }
    }

    const float4* W4 = reinterpret_cast<const float4*>(W);
    if (MODE == 1) {
#pragma unroll
        for (int i = 0; i < 5; i++) {
            int f = tid + i * 128;       // 0..639
            int kr = f >> 4, nc = f & 15;
            float4 v = W4[(size_t)(k0 + kr) * (DD / 4) + (n0 >> 2) + nc];
            reinterpret_cast<float4*>(&Ws[kr][0])[nc] = v;
        }
    } else {
#pragma unroll
        for (int i = 0; i < 5; i++) {
            int f = tid + i * 128;
            int n = f / 10, kc4 = f % 10;
            float4 v = W4[(size_t)(n0 + n) * (DD / 4) + k04 + kc4];
            Ws[kc4 * 4 + 0][n] = v.x;
            Ws[kc4 * 4 + 1][n] = v.y;
            Ws[kc4 * 4 + 2][n] = v.z;
            Ws[kc4 * 4 + 3][n] = v.w;
        }
    }
    __syncthreads();

    const int tx = tid & 15;
    const int ty = tid >> 4;             // 0..7

    float acc[4][4] = {};
#pragma unroll 8
    for (int k = 0; k < KC; k++) {
        float a[4];
#pragma unroll
        for (int i = 0; i < 4; i++) a[i] = As[k][ty + 8 * i];
        const float4 w = reinterpret_cast<const float4*>(&Ws[k][0])[tx];
#pragma unroll
        for (int i = 0; i < 4; i++) {
            acc[i][0] = fmaf(a[i], w.x, acc[i][0]);
            acc[i][1] = fmaf(a[i], w.y, acc[i][1]);
            acc[i][2] = fmaf(a[i], w.z, acc[i][2]);
            acc[i][3] = fmaf(a[i], w.w, acc[i][3]);
        }
    }

#pragma unroll
    for (int i = 0; i < 4; i++)
        red_add_v4(&C[(size_t)(ty + 8 * i) * DD + n0 + tx * 4],
                   acc[i][0], acc[i][1], acc[i][2], acc[i][3]);
}

// ---------------------------------------------------------------------------
// attention + pooling — R12-exact loop (frozen), + last-CTA combine tail.
// grid 512 (32 b x 16 CTAs), block 128 (4 warps x 16 rows), manual prefetch.
// ---------------------------------------------------------------------------
__global__ void __launch_bounds__(128) attn_kernel(const float* __restrict__ emb,
                                                   const int* __restrict__ mask,
                                                   const float* __restrict__ bk,
                                                   float scale)
{
    __shared__ float skq[DD];
    __shared__ float4 sacc[WPB][DD / 4];
    __shared__ float sm[WPB], sl[WPB], scb;
    __shared__ unsigned s_done;
    __shared__ float cfs[NCP];

    const int b = blockIdx.x / CTAS_PER_B;
    const int cta = blockIdx.x % CTAS_PER_B;
    const int tid = threadIdx.x;
    const int warp = tid >> 5;
    const int lane = tid & 31;
    const int split = cta * WPB + warp;
    const int s0 = split * RPW;

    {
        const float4* src = reinterpret_cast<const float4*>(g_kq + b * DD);
        float4* dst = reinterpret_cast<float4*>(skq);
        for (int i = tid; i < DD / 4; i += 128) dst[i] = src[i];
    }
    if (warp == 0) {
        const float4* q04 = reinterpret_cast<const float4*>(g_q0 + b * DD);
        const float4* bk4 = reinterpret_cast<const float4*>(bk);
        float p = 0.0f;
#pragma unroll
        for (int c = 0; c < 10; c++) {
            const float4 q = q04[c * 32 + lane];
            const float4 k = bk4[c * 32 + lane];
            p = fmaf(q.x, k.x, p); p = fmaf(q.y, k.y, p);
            p = fmaf(q.z, k.z, p); p = fmaf(q.w, k.w, p);
        }
#pragma unroll
        for (int off = 16; off > 0; off >>= 1)
            p += __shfl_xor_sync(0xffffffffu, p, off);
        if (lane == 0) scb = p;
    }

    const float* base = emb + (size_t)b * SS * DD;
    float4 x[10];
    {
        const float4* row = reinterpret_cast<const float4*>(base + (size_t)s0 * DD);
#pragma unroll
        for (int c = 0; c < 10; c++) x[c] = row[c * 32 + lane];
    }
    const int* mrow = mask + b * SS;

    __syncthreads();
    const float cb = scb;

    float m = -INFINITY, l = 0.0f;
    float4 acc[10];
#pragma unroll
    for (int c = 0; c < 10; c++) acc[c] = make_float4(0.f, 0.f, 0.f, 0.f);

#pragma unroll 4
    for (int r = 0; r < RPW; r++) {
        const int s = s0 + r;
        const int mk = mrow[s];

        float4 y[10];
        {
            const int rn = (r + 1 < RPW) ? r + 1 : r;
            const float4* nrow =
                reinterpret_cast<const float4*>(base + (size_t)(s0 + rn) * DD);
#pragma unroll
            for (int c = 0; c < 10; c++) y[c] = nrow[c * 32 + lane];
        }

        float p = 0.0f;
        const float4* kq4 = reinterpret_cast<const float4*>(skq);
#pragma unroll
        for (int c = 0; c < 10; c++) {
            const float4 k = kq4[c * 32 + lane];
            p = fmaf(x[c].x, k.x, p);
            p = fmaf(x[c].y, k.y, p);
            p = fmaf(x[c].z, k.z, p);
            p = fmaf(x[c].w, k.w, p);
        }
#pragma unroll
        for (int off = 16; off > 0; off >>= 1)
            p += __shfl_xor_sync(0xffffffffu, p, off);

        float score = (p + cb) * scale;
        if (mk == 0) score = -1e9f;

        const float mn = fmaxf(m, score);
        if (mn > m) {
            const float fac = __expf(m - mn);
            l *= fac;
#pragma unroll
            for (int c = 0; c < 10; c++) {
                acc[c].x *= fac; acc[c].y *= fac;
                acc[c].z *= fac; acc[c].w *= fac;
            }
            m = mn;
        }
        const float w = __expf(score - m);
        l += w;
#pragma unroll
        for (int c = 0; c < 10; c++) {
            acc[c].x = fmaf(w, x[c].x, acc[c].x);
            acc[c].y = fmaf(w, x[c].y, acc[c].y);
            acc[c].z = fmaf(w, x[c].z, acc[c].z);
            acc[c].w = fmaf(w, x[c].w, acc[c].w);
        }
#pragma unroll
        for (int c = 0; c < 10; c++) x[c] = y[c];
    }

#pragma unroll
    for (int c = 0; c < 10; c++) sacc[warp][c * 32 + lane] = acc[c];
    if (lane == 0) { sm[warp] = m; sl[warp] = l; }
    __syncthreads();

    const float M = fmaxf(fmaxf(sm[0], sm[1]), fmaxf(sm[2], sm[3]));
    const float f0 = __expf(sm[0] - M), f1 = __expf(sm[1] - M);
    const float f2 = __expf(sm[2] - M), f3 = __expf(sm[3] - M);
    const float L = f0 * sl[0] + f1 * sl[1] + f2 * sl[2] + f3 * sl[3];

    const int pidx = b * NCP + cta;
    float4* pa = reinterpret_cast<float4*>(g_pacc + (size_t)pidx * DD);
#pragma unroll
    for (int i = 0; i < 3; i++) {
        const int idx = tid + i * 128;
        if (idx < DD / 4) {
            const float4 a0 = sacc[0][idx], a1 = sacc[1][idx];
            const float4 a2 = sacc[2][idx], a3 = sacc[3][idx];
            float4 s;
            s.x = fmaf(f0, a0.x, fmaf(f1, a1.x, fmaf(f2, a2.x, f3 * a3.x)));
            s.y = fmaf(f0, a0.y, fmaf(f1, a1.y, fmaf(f2, a2.y, f3 * a3.y)));
            s.z = fmaf(f0, a0.z, fmaf(f1, a1.z, fmaf(f2, a2.z, f3 * a3.z)));
            s.w = fmaf(f0, a0.w, fmaf(f1, a1.w, fmaf(f2, a2.w, f3 * a3.w)));
            pa[idx] = s;
        }
    }
    if (tid == 0) { g_pm[pidx] = M; g_pl[pidx] = L; }

    // ---- last-CTA-per-batch combine: 16th arrival folds the 16 partials ----
    __threadfence();
    __syncthreads();
    if (tid == 0) s_done = atomicAdd(&g_cnt[b], 1u);
    __syncthreads();
    if (s_done == NCP - 1) {
        if (warp == 0) {
            const float pm = (lane < NCP) ? __ldcg(&g_pm[b * NCP + lane])
                                          : -INFINITY;
            const float pl = (lane < NCP) ? __ldcg(&g_pl[b * NCP + lane]) : 0.f;
            float Mx = pm;
#pragma unroll
            for (int off = 16; off > 0; off >>= 1)
                Mx = fmaxf(Mx, __shfl_xor_sync(0xffffffffu, Mx, off));
            const float f = (lane < NCP) ? __expf(pm - Mx) : 0.0f;
            float Lx = f * pl;
#pragma unroll
            for (int off = 16; off > 0; off >>= 1)
                Lx += __shfl_xor_sync(0xffffffffu, Lx, off);
            if (lane < NCP) cfs[lane] = f / Lx;
        }
        __syncthreads();

        const float4* pacc4 = reinterpret_cast<const float4*>(
            g_pacc + (size_t)b * NCP * DD);
        float4* pooled4 = reinterpret_cast<float4*>(g_pooled + b * DD);
#pragma unroll
        for (int i = 0; i < 3; i++) {
            const int idx = tid + i * 128;
            if (idx < DD / 4) {
                float4 s = make_float4(0.f, 0.f, 0.f, 0.f);
#pragma unroll
                for (int p = 0; p < NCP; p++) {
                    const float f = cfs[p];
                    const float4 a = __ldcg(&pacc4[(size_t)p * (DD / 4) + idx]);
                    s.x = fmaf(f, a.x, s.x);
                    s.y = fmaf(f, a.y, s.y);
                    s.z = fmaf(f, a.z, s.z);
                    s.w = fmaf(f, a.w, s.w);
                }
                pooled4[idx] = s;
            }
        }
    }
}

// ---------------------------------------------------------------------------
// LayerNorm + ReLU on g_h[32,1280] -> out. grid 32, block 320 (shuffle reduce).
// ---------------------------------------------------------------------------
__global__ void __launch_bounds__(320) ln_kernel(const float* __restrict__ gamma,
                                                 const float* __restrict__ beta,
                                                 float* __restrict__ out)
{
    const int b = blockIdx.x, tid = threadIdx.x;   // tid = float4 idx
    const int warp = tid >> 5, lane = tid & 31;

    const float4 s = reinterpret_cast<const float4*>(g_h)[b * (DD / 4) + tid];

    float sum = s.x + s.y + s.z + s.w;
    float sq  = s.x * s.x + s.y * s.y + s.z * s.z + s.w * s.w;
#pragma unroll
    for (int off = 16; off > 0; off >>= 1) {
        sum += __shfl_xor_sync(0xffffffffu, sum, off);
        sq  += __shfl_xor_sync(0xffffffffu, sq,  off);
    }
    __shared__ float rs[10], rq[10];
    __shared__ float smu, sinv;
    if (lane == 0) { rs[warp] = sum; rq[warp] = sq; }
    __syncthreads();
    if (tid == 0) {
        float S = 0.f, Q = 0.f;
#pragma unroll
        for (int w = 0; w < 10; w++) { S += rs[w]; Q += rq[w]; }
        const float mu = S * (1.0f / DD);
        float var = Q * (1.0f / DD) - mu * mu;
        var = fmaxf(var, 0.0f);
        smu = mu;
        sinv = rsqrtf(var + 1e-5f);
    }
    __syncthreads();
    const float mu = smu, inv = sinv;

    const float4 g  = reinterpret_cast<const float4*>(gamma)[tid];
    const float4 be = reinterpret_cast<const float4*>(beta)[tid];
    float4 o;
    o.x = fmaxf(fmaf((s.x - mu) * inv, g.x, be.x), 0.0f);
    o.y = fmaxf(fmaf((s.y - mu) * inv, g.y, be.y), 0.0f);
    o.z = fmaxf(fmaf((s.z - mu) * inv, g.z, be.z), 0.0f);
    o.w = fmaxf(fmaf((s.w - mu) * inv, g.w, be.w), 0.0f);
    reinterpret_cast<float4*>(out)[b * (DD / 4) + tid] = o;
}

// ---------------------------------------------------------------------------
extern "C" void kernel_launch(void* const* d_in, const int* in_sizes, int n_in,
                              void* d_out, int out_size)
{
    (void)in_sizes; (void)n_in; (void)out_size;

    const float* emb   = (const float*)d_in[0];
    const int*   mask  = (const int*)d_in[1];
    const float* Wq    = (const float*)d_in[2];
    const float* bq    = (const float*)d_in[3];
    const float* Wk    = (const float*)d_in[4];
    const float* bk    = (const float*)d_in[5];
    const float* Wv    = (const float*)d_in[6];
    const float* bv    = (const float*)d_in[7];
    const float* Wo    = (const float*)d_in[8];
    const float* bo    = (const float*)d_in[9];
    const float* gamma = (const float*)d_in[10];
    const float* beta  = (const float*)d_in[11];
    float* out = (float*)d_out;

    const float scale = 1.0f / sqrtf((float)DD);
    const dim3 ggrid(DD / 64, 32);   // 20 n-tiles x 32 k-splits = 640 CTAs

    init_kernel<<<(BB * DD + 255) / 256, 256>>>(bq, bv, bo);
    gemm32<0, 0, 0><<<ggrid, 128>>>(emb, (size_t)SS * DD, Wq);     // q0
    gemm32<1, 1, 1><<<ggrid, 128>>>(nullptr, 0, Wk);               // kq = q0@Wk
    attn_kernel<<<BB * CTAS_PER_B, 128>>>(emb, mask, bk, scale);   // pool+combine
    gemm32<0, 2, 2><<<ggrid, 128>>>(nullptr, 0, Wv);               // ctx
    gemm32<0, 3, 3><<<ggrid, 128>>>(nullptr, 0, Wo);               // h
    ln_kernel<<<BB, 320>>>(gamma, beta, out);
}

// round 16
// speedup vs baseline: 1.0448x; 1.0448x over previous
#include <cuda_runtime.h>
#include <math.h>

// ---------------------------------------------------------------------------
// ProteinEmbeddingPooling — 3 launches (was 7; T_ovh ~3us/launch dominated):
//   megaA: init-seed ; bar ; gemm q0 (RED) ; bar ; gemm kq (RED)
//   attn : R14-exact online-softmax split-S pooling (FROZEN)
//   megaB: combine ; bar ; gemm ctx ; bar ; gemm h ; bar ; LayerNorm+ReLU
// Grid barriers: monotone counter + release word, nanosleep-backoff polling.
// Counters mutually reset (megaA zeros B's, megaB zeros A's) — graph-safe.
// ---------------------------------------------------------------------------

#define BB 32
#define SS 1024
#define DD 1280
#define NCTA 640                         // mega kernels: 20 n-tiles x 32 ks
#define CTAS_PER_B 16
#define WPB 4
#define NCP CTAS_PER_B                   // attn partials per batch
#define RPW (SS / (CTAS_PER_B * WPB))    // 16 rows per warp

// ---- scratch (device globals; no allocation allowed) ----
__device__ float g_q0[BB * DD];
__device__ float g_kq[BB * DD];
__device__ float g_ctx[BB * DD];
__device__ float g_h[BB * DD];
__device__ float g_pm[BB * NCP];
__device__ float g_pl[BB * NCP];
__device__ float g_pacc[(size_t)BB * NCP * DD];      // 2.6 MB
__device__ float g_pooled[BB * DD];
__device__ unsigned g_cntA, g_relA, g_cntB, g_relB;  // zero-initialized

__device__ __forceinline__ void red_add_v4(float* p, float a, float b,
                                           float c, float d)
{
    asm volatile("red.global.add.v4.f32 [%0], {%1, %2, %3, %4};"
                 :: "l"(p), "f"(a), "f"(b), "f"(c), "f"(d) : "memory");
}

// grid barrier #k (k = 1, 2, ...): monotone counter, monotone release word.
__device__ __forceinline__ void gbarrier(unsigned* cnt, unsigned* rel,
                                         unsigned k)
{
    __syncthreads();
    if (threadIdx.x == 0) {
        __threadfence();
        const unsigned pos = atomicAdd(cnt, 1u) + 1u;
        if (pos == k * NCTA) {
            atomicExch(rel, k);
        } else {
            while (__ldcg(rel) < k) __nanosleep(128);
        }
        __threadfence();
    }
    __syncthreads();
}

// ---------------------------------------------------------------------------
// gemm phase: C[32,1280] += A[32,1280-slice] * op(W-slice)  (R14-exact math)
//   MODE 0: W [N,K] row-major ; MODE 1: W [K,N] row-major
//   SRC: 0 = Aext (external, __ldg), 1 = g_q0, 2 = g_pooled, 3 = g_ctx (__ldcg)
// 640 CTAs x 128 thr; bx -> (n0 = (bx%20)*64, ks = bx/20, k0 = ks*40).
// ---------------------------------------------------------------------------
template<int MODE, int SRC>
__device__ __forceinline__ void gemm_phase(const float* Aext, size_t lda,
                                           const float* __restrict__ W,
                                           float* C,
                                           float (&As)[40][33],
                                           float (&Ws)[40][68])
{
    constexpr int KC = 40;
    const float* A = (SRC == 0) ? Aext
                   : (SRC == 1) ? g_q0
                   : (SRC == 2) ? g_pooled
                   :              g_ctx;
    if (SRC != 0) lda = DD;

    const int tid = threadIdx.x;
    const int n0 = (blockIdx.x % 20) * 64;
    const int k0 = (blockIdx.x / 20) * KC;
    const int k04 = k0 >> 2;

    const float4* A4 = reinterpret_cast<const float4*>(A);
    const size_t lda4 = lda >> 2;
#pragma unroll
    for (int i = 0; i < 3; i++) {
        int f = tid + i * 128;
        if (f < 320) {
            int m = f / 10, kc4 = f % 10;
            const float4* ap = &A4[(size_t)m * lda4 + k04 + kc4];
            float4 v = (SRC == 0) ? __ldg(ap) : __ldcg(ap);
            As[kc4 * 4 + 0][m] = v.x;
            As[kc4 * 4 + 1][m] = v.y;
            As[kc4 * 4 + 2][m] = v.z;
            As[kc4 * 4 + 3][m] = v.w;
        }
    }

    const float4* W4 = reinterpret_cast<const float4*>(W);
    if (MODE == 1) {
#pragma unroll
        for (int i = 0; i < 5; i++) {
            int f = tid + i * 128;       // 0..639
            int kr = f >> 4, nc = f & 15;
            float4 v = __ldg(&W4[(size_t)(k0 + kr) * (DD / 4) + (n0 >> 2) + nc]);
            reinterpret_cast<float4*>(&Ws[kr][0])[nc] = v;
        }
    } else {
#pragma unroll
        for (int i = 0; i < 5; i++) {
            int f = tid + i * 128;
            int n = f / 10, kc4 = f % 10;
            float4 v = __ldg(&W4[(size_t)(n0 + n) * (DD / 4) + k04 + kc4]);
            Ws[kc4 * 4 + 0][n] = v.x;
            Ws[kc4 * 4 + 1][n] = v.y;
            Ws[kc4 * 4 + 2][n] = v.z;
            Ws[kc4 * 4 + 3][n] = v.w;
        }
    }
    __syncthreads();

    const int tx = tid & 15;
    const int ty = tid >> 4;             // 0..7

    float acc[4][4] = {};
#pragma unroll 8
    for (int k = 0; k < KC; k++) {
        float a[4];
#pragma unroll
        for (int i = 0; i < 4; i++) a[i] = As[k][ty + 8 * i];
        const float4 w = reinterpret_cast<const float4*>(&Ws[k][0])[tx];
#pragma unroll
        for (int i = 0; i < 4; i++) {
            acc[i][0] = fmaf(a[i], w.x, acc[i][0]);
            acc[i][1] = fmaf(a[i], w.y, acc[i][1]);
            acc[i][2] = fmaf(a[i], w.z, acc[i][2]);
            acc[i][3] = fmaf(a[i], w.w, acc[i][3]);
        }
    }

#pragma unroll
    for (int i = 0; i < 4; i++)
        red_add_v4(&C[(size_t)(ty + 8 * i) * DD + n0 + tx * 4],
                   acc[i][0], acc[i][1], acc[i][2], acc[i][3]);
}

// ---------------------------------------------------------------------------
// megaA: init-seed ; bar ; gemm q0 ; bar ; gemm kq
// ---------------------------------------------------------------------------
__global__ void __launch_bounds__(128, 5) megaA(const float* __restrict__ emb,
                                                const float* __restrict__ Wq,
                                                const float* __restrict__ bq,
                                                const float* __restrict__ Wk,
                                                const float* __restrict__ bv,
                                                const float* __restrict__ bo)
{
    __shared__ float As[40][33];
    __shared__ float Ws[40][68];

    // phase 0: bias-seed C matrices + zero megaB's barrier state
    const int i = blockIdx.x * 128 + threadIdx.x;   // 0..81919
    if (i < BB * DD) {
        const int n = i % DD;
        g_q0[i]  = __ldg(&bq[n]);
        g_kq[i]  = 0.0f;
        g_ctx[i] = __ldg(&bv[n]);
        g_h[i]   = __ldg(&bo[n]);
    }
    if (i == 0) { g_cntB = 0u; g_relB = 0u; }

    gbarrier(&g_cntA, &g_relA, 1u);
    gemm_phase<0, 0>(emb, (size_t)SS * DD, Wq, g_q0, As, Ws);   // q0
    gbarrier(&g_cntA, &g_relA, 2u);
    gemm_phase<1, 1>(nullptr, 0, Wk, g_kq, As, Ws);             // kq = q0@Wk
}

// ---------------------------------------------------------------------------
// megaB: combine ; bar ; gemm ctx ; bar ; gemm h ; bar ; LN+ReLU
// ---------------------------------------------------------------------------
__global__ void __launch_bounds__(128, 5) megaB(const float* __restrict__ Wv,
                                                const float* __restrict__ Wo,
                                                const float* __restrict__ gamma,
                                                const float* __restrict__ beta,
                                                float* __restrict__ out)
{
    __shared__ float As[40][33];
    __shared__ float Ws[40][68];
    __shared__ float rs[4], rq[4];
    __shared__ float smu, sinv;

    const int tid = threadIdx.x;
    const int bx = blockIdx.x;

    if (bx == 0 && tid == 0) { g_cntA = 0u; g_relA = 0u; }

    // phase 0: combine 16 attn partials -> pooled (first 320 CTAs, 1 out/thr)
    if (bx < 320) {
        const int o = bx * 128 + tid;   // 0..40959
        const int b = o / DD;
        const int d = o - b * DD;

        float M = -INFINITY;
#pragma unroll
        for (int p = 0; p < NCP; p++) M = fmaxf(M, __ldg(&g_pm[b * NCP + p]));
        float L = 0.0f, s = 0.0f;
#pragma unroll
        for (int p = 0; p < NCP; p++) {
            const float f = __expf(__ldg(&g_pm[b * NCP + p]) - M);
            L = fmaf(f, __ldg(&g_pl[b * NCP + p]), L);
            s = fmaf(f, __ldg(&g_pacc[(size_t)(b * NCP + p) * DD + d]), s);
        }
        g_pooled[o] = s / L;
    }

    gbarrier(&g_cntB, &g_relB, 1u);
    gemm_phase<0, 2>(nullptr, 0, Wv, g_ctx, As, Ws);            // ctx
    gbarrier(&g_cntB, &g_relB, 2u);
    gemm_phase<0, 3>(nullptr, 0, Wo, g_h, As, Ws);              // h
    gbarrier(&g_cntB, &g_relB, 3u);

    // phase 3: LayerNorm + ReLU (CTAs 0..31, one batch row each, 10 elems/thr)
    if (bx < BB) {
        const int b = bx;
        const int warp = tid >> 5, lane = tid & 31;
        float x[10];
        float sum = 0.0f, sq = 0.0f;
#pragma unroll
        for (int j = 0; j < 10; j++) {
            x[j] = __ldcg(&g_h[b * DD + tid + j * 128]);
            sum += x[j];
            sq = fmaf(x[j], x[j], sq);
        }
#pragma unroll
        for (int off = 16; off > 0; off >>= 1) {
            sum += __shfl_xor_sync(0xffffffffu, sum, off);
            sq  += __shfl_xor_sync(0xffffffffu, sq,  off);
        }
        if (lane == 0) { rs[warp] = sum; rq[warp] = sq; }
        __syncthreads();
        if (tid == 0) {
            const float S = rs[0] + rs[1] + rs[2] + rs[3];
            const float Q = rq[0] + rq[1] + rq[2] + rq[3];
            const float mu = S * (1.0f / DD);
            float var = Q * (1.0f / DD) - mu * mu;
            var = fmaxf(var, 0.0f);
            smu = mu;
            sinv = rsqrtf(var + 1e-5f);
        }
        __syncthreads();
        const float mu = smu, inv = sinv;
#pragma unroll
        for (int j = 0; j < 10; j++) {
            const int n = tid + j * 128;
            const float v = (x[j] - mu) * inv * __ldg(&gamma[n]) + __ldg(&beta[n]);
            out[b * DD + n] = fmaxf(v, 0.0f);
        }
    }
}

// ---------------------------------------------------------------------------
// attention + pooling — R14-exact (empirical best: 35.9us). FROZEN.
// grid 512 (32 b x 16 CTAs), block 128 (4 warps x 16 rows), manual prefetch.
// ---------------------------------------------------------------------------
__global__ void __launch_bounds__(128) attn_kernel(const float* __restrict__ emb,
                                                   const int* __restrict__ mask,
                                                   const float* __restrict__ bk,
                                                   float scale)
{
    __shared__ float skq[DD];
    __shared__ float4 sacc[WPB][DD / 4];
    __shared__ float sm[WPB], sl[WPB], scb;

    const int b = blockIdx.x / CTAS_PER_B;
    const int cta = blockIdx.x % CTAS_PER_B;
    const int tid = threadIdx.x;
    const int warp = tid >> 5;
    const int lane = tid & 31;
    const int split = cta * WPB + warp;
    const int s0 = split * RPW;

    {
        const float4* src = reinterpret_cast<const float4*>(g_kq + b * DD);
        float4* dst = reinterpret_cast<float4*>(skq);
        for (int i = tid; i < DD / 4; i += 128) dst[i] = src[i];
    }
    if (warp == 0) {
        const float4* q04 = reinterpret_cast<const float4*>(g_q0 + b * DD);
        const float4* bk4 = reinterpret_cast<const float4*>(bk);
        float p = 0.0f;
#pragma unroll
        for (int c = 0; c < 10; c++) {
            const float4 q = q04[c * 32 + lane];
            const float4 k = bk4[c * 32 + lane];
            p = fmaf(q.x, k.x, p); p = fmaf(q.y, k.y, p);
            p = fmaf(q.z, k.z, p); p = fmaf(q.w, k.w, p);
        }
#pragma unroll
        for (int off = 16; off > 0; off >>= 1)
            p += __shfl_xor_sync(0xffffffffu, p, off);
        if (lane == 0) scb = p;
    }

    const float* base = emb + (size_t)b * SS * DD;
    float4 x[10];
    {
        const float4* row = reinterpret_cast<const float4*>(base + (size_t)s0 * DD);
#pragma unroll
        for (int c = 0; c < 10; c++) x[c] = row[c * 32 + lane];
    }
    const int* mrow = mask + b * SS;

    __syncthreads();
    const float cb = scb;

    float m = -INFINITY, l = 0.0f;
    float4 acc[10];
#pragma unroll
    for (int c = 0; c < 10; c++) acc[c] = make_float4(0.f, 0.f, 0.f, 0.f);

#pragma unroll 4
    for (int r = 0; r < RPW; r++) {
        const int s = s0 + r;
        const int mk = mrow[s];

        float4 y[10];
        {
            const int rn = (r + 1 < RPW) ? r + 1 : r;
            const float4* nrow =
                reinterpret_cast<const float4*>(base + (size_t)(s0 + rn) * DD);
#pragma unroll
            for (int c = 0; c < 10; c++) y[c] = nrow[c * 32 + lane];
        }

        float p = 0.0f;
        const float4* kq4 = reinterpret_cast<const float4*>(skq);
#pragma unroll
        for (int c = 0; c < 10; c++) {
            const float4 k = kq4[c * 32 + lane];
            p = fmaf(x[c].x, k.x, p);
            p = fmaf(x[c].y, k.y, p);
            p = fmaf(x[c].z, k.z, p);
            p = fmaf(x[c].w, k.w, p);
        }
#pragma unroll
        for (int off = 16; off > 0; off >>= 1)
            p += __shfl_xor_sync(0xffffffffu, p, off);

        float score = (p + cb) * scale;
        if (mk == 0) score = -1e9f;

        const float mn = fmaxf(m, score);
        if (mn > m) {
            const float fac = __expf(m - mn);
            l *= fac;
#pragma unroll
            for (int c = 0; c < 10; c++) {
                acc[c].x *= fac; acc[c].y *= fac;
                acc[c].z *= fac; acc[c].w *= fac;
            }
            m = mn;
        }
        const float w = __expf(score - m);
        l += w;
#pragma unroll
        for (int c = 0; c < 10; c++) {
            acc[c].x = fmaf(w, x[c].x, acc[c].x);
            acc[c].y = fmaf(w, x[c].y, acc[c].y);
            acc[c].z = fmaf(w, x[c].z, acc[c].z);
            acc[c].w = fmaf(w, x[c].w, acc[c].w);
        }
#pragma unroll
        for (int c = 0; c < 10; c++) x[c] = y[c];
    }

#pragma unroll
    for (int c = 0; c < 10; c++) sacc[warp][c * 32 + lane] = acc[c];
    if (lane == 0) { sm[warp] = m; sl[warp] = l; }
    __syncthreads();

    const float M = fmaxf(fmaxf(sm[0], sm[1]), fmaxf(sm[2], sm[3]));
    const float f0 = __expf(sm[0] - M), f1 = __expf(sm[1] - M);
    const float f2 = __expf(sm[2] - M), f3 = __expf(sm[3] - M);
    const float L = f0 * sl[0] + f1 * sl[1] + f2 * sl[2] + f3 * sl[3];

    const int pidx = b * NCP + cta;
    float4* pa = reinterpret_cast<float4*>(g_pacc + (size_t)pidx * DD);
#pragma unroll
    for (int i = 0; i < 3; i++) {
        const int idx = tid + i * 128;
        if (idx < DD / 4) {
            const float4 a0 = sacc[0][idx], a1 = sacc[1][idx];
            const float4 a2 = sacc[2][idx], a3 = sacc[3][idx];
            float4 s;
            s.x = fmaf(f0, a0.x, fmaf(f1, a1.x, fmaf(f2, a2.x, f3 * a3.x)));
            s.y = fmaf(f0, a0.y, fmaf(f1, a1.y, fmaf(f2, a2.y, f3 * a3.y)));
            s.z = fmaf(f0, a0.z, fmaf(f1, a1.z, fmaf(f2, a2.z, f3 * a3.z)));
            s.w = fmaf(f0, a0.w, fmaf(f1, a1.w, fmaf(f2, a2.w, f3 * a3.w)));
            pa[idx] = s;
        }
    }
    if (tid == 0) { g_pm[pidx] = M; g_pl[pidx] = L; }
}

// ---------------------------------------------------------------------------
extern "C" void kernel_launch(void* const* d_in, const int* in_sizes, int n_in,
                              void* d_out, int out_size)
{
    (void)in_sizes; (void)n_in; (void)out_size;

    const float* emb   = (const float*)d_in[0];
    const int*   mask  = (const int*)d_in[1];
    const float* Wq    = (const float*)d_in[2];
    const float* bq    = (const float*)d_in[3];
    const float* Wk    = (const float*)d_in[4];
    const float* bk    = (const float*)d_in[5];
    const float* Wv    = (const float*)d_in[6];
    const float* bv    = (const float*)d_in[7];
    const float* Wo    = (const float*)d_in[8];
    const float* bo    = (const float*)d_in[9];
    const float* gamma = (const float*)d_in[10];
    const float* beta  = (const float*)d_in[11];
    float* out = (float*)d_out;

    const float scale = 1.0f / sqrtf((float)DD);

    megaA<<<NCTA, 128>>>(emb, Wq, bq, Wk, bv, bo);
    attn_kernel<<<BB * CTAS_PER_B, 128>>>(emb, mask, bk, scale);
    megaB<<<NCTA, 128>>>(Wv, Wo, gamma, beta, out);
}